// round 1
// baseline (speedup 1.0000x reference)
#include <cuda_runtime.h>

// GateRecurrent2dnoind: H[:,:,h,w] = B*X + G1*H[h-1,w-1] + G2*H[h,w-1] + G3*H[h+1,w-1]
// Shape (8, 96, 128, 128) -> 768 independent (H=128, W=128) planes.
//
// Strategy: one block per plane, one thread per row h. The recurrent column
// H[:, w-1] lives in shared memory, double-buffered, with zero halos at
// index 0 and H+1 so the h-1 / h+1 taps need no branches. One __syncthreads
// per W-step. Inputs are streamed 8 floats (two float4) at a time per thread
// so every 32B DRAM sector a thread touches is fully consumed; outputs are
// accumulated in registers and written back as two float4 per 8 steps.
// All 768 blocks are co-resident (~5/SM), so the per-block serial critical
// path (~13K cycles) hides under the ~46us HBM floor (302 MB total traffic).

#define H_DIM 128
#define W_DIM 128
#define CHUNK 8
#define NCHUNK (W_DIM / CHUNK)

__device__ __forceinline__ void load8(const float* __restrict__ p, float r[CHUNK]) {
    float4 a = *(const float4*)(p);
    float4 b = *(const float4*)(p + 4);
    r[0] = a.x; r[1] = a.y; r[2] = a.z; r[3] = a.w;
    r[4] = b.x; r[5] = b.y; r[6] = b.z; r[7] = b.w;
}

__global__ void __launch_bounds__(H_DIM)
gaterec_kernel(const float* __restrict__ X,  const float* __restrict__ B,
               const float* __restrict__ G1, const float* __restrict__ G2,
               const float* __restrict__ G3, float* __restrict__ Out)
{
    const int h = threadIdx.x;                       // row within the plane
    const size_t base = (size_t)blockIdx.x * (H_DIM * W_DIM) + (size_t)h * W_DIM;

    // Double-buffered recurrent column with zero halos.
    // hcol[p][0] and hcol[p][H+1] stay 0 forever; row h lives at index h+1.
    __shared__ float hcol[2][H_DIM + 2];
    hcol[0][h + 1] = 0.0f;                           // column w = -1 is all zeros
    if (h < 2) {
        hcol[0][h * (H_DIM + 1)] = 0.0f;             // indices 0 and H+1
        hcol[1][h * (H_DIM + 1)] = 0.0f;
    }
    __syncthreads();

    const float* xp  = X  + base;
    const float* bp  = B  + base;
    const float* g1p = G1 + base;
    const float* g2p = G2 + base;
    const float* g3p = G3 + base;
    float*       op  = Out + base;

    #pragma unroll
    for (int c = 0; c < NCHUNK; ++c) {
        const int w0 = c * CHUNK;
        float xv[CHUNK], bv[CHUNK], g1v[CHUNK], g2v[CHUNK], g3v[CHUNK], o[CHUNK];
        load8(xp  + w0, xv);
        load8(bp  + w0, bv);
        load8(g1p + w0, g1v);
        load8(g2p + w0, g2v);
        load8(g3p + w0, g3v);

        #pragma unroll
        for (int i = 0; i < CHUNK; ++i) {
            const int cur = i & 1;                   // CHUNK is even -> phase resets per chunk
            float up  = hcol[cur][h];                // H[h-1, w-1]
            float mid = hcol[cur][h + 1];            // H[h,   w-1]
            float dn  = hcol[cur][h + 2];            // H[h+1, w-1]
            float hn = fmaf(bv[i], xv[i],
                       fmaf(g1v[i], up,
                       fmaf(g2v[i], mid, g3v[i] * dn)));
            hcol[cur ^ 1][h + 1] = hn;
            o[i] = hn;
            __syncthreads();                         // writes to cur^1 visible next step
        }

        *(float4*)(op + w0)     = make_float4(o[0], o[1], o[2], o[3]);
        *(float4*)(op + w0 + 4) = make_float4(o[4], o[5], o[6], o[7]);
    }
}

extern "C" void kernel_launch(void* const* d_in, const int* in_sizes, int n_in,
                              void* d_out, int out_size) {
    const float* X  = (const float*)d_in[0];
    const float* B  = (const float*)d_in[1];
    const float* G1 = (const float*)d_in[2];
    const float* G2 = (const float*)d_in[3];
    const float* G3 = (const float*)d_in[4];
    float* Out = (float*)d_out;

    const int planes = in_sizes[0] / (H_DIM * W_DIM);   // N*C = 768
    gaterec_kernel<<<planes, H_DIM>>>(X, B, G1, G2, G3, Out);
}

// round 2
// speedup vs baseline: 1.7567x; 1.7567x over previous
#include <cuda_runtime.h>
#include <cstdint>

// GateRecurrent2dnoind: H[:,:,h,w] = B*X + G1*H[h-1,w-1] + G2*H[h,w-1] + G3*H[h+1,w-1]
// (8, 96, 128, 128) -> 768 independent (128 x 128) planes, serial scan over W.
//
// Round-2 design: the R1 kernel was L1tex-wavefront-bound (63.5% L1, 32 lines
// per strided LDG.128). This version stages all gmem traffic through shared
// memory with coalesced cp.async (8 lines/instr) and a coalesced cooperative
// store, while keeping the register-resident serial recurrence:
//   - chunk = 16 columns; 5 input tiles (128 x 16, row-padded to 20 floats)
//     double-buffered, filled by cp.async.cg with a warp mapping that touches
//     8 consecutive rows per instruction.
//   - compute thread h reads its own row from smem (LDS.128, stride-20 rows:
//     16B-aligned and bank-conflict-free), runs 8-step sub-chunks from regs.
//   - per-step recurrent column in a double-buffered smem array with zero halos.
//   - outputs staged in a padded smem tile (conflict-free scalar STS), then
//     written back with the same coalesced 8-row mapping.
//   - 2-deep cp.async pipeline (prefetch chunk c+2 during chunk c).

#define H_DIM   128
#define W_DIM   128
#define CW      16                  // staged chunk width (columns)
#define NCH     (W_DIM / CW)        // 8 chunks
#define SUB     8                   // register sub-chunk width
#define RSTRIDE 20                  // padded row stride (floats): 80B, 16B-aligned, bank-clean
#define TILE_F  (H_DIM * RSTRIDE)   // 2560 floats per array tile
#define NARR    5

__device__ __forceinline__ void cp_async16(uint32_t dst, const float* src) {
    asm volatile("cp.async.cg.shared.global [%0], [%1], 16;\n" :: "r"(dst), "l"(src));
}
__device__ __forceinline__ void cp_commit() {
    asm volatile("cp.async.commit_group;\n" ::: "memory");
}
template <int N>
__device__ __forceinline__ void cp_wait() {
    asm volatile("cp.async.wait_group %0;\n" :: "n"(N) : "memory");
}

__device__ __forceinline__ void lds8(const float* __restrict__ p, float r[SUB]) {
    float4 a = *(const float4*)(p);
    float4 b = *(const float4*)(p + 4);
    r[0] = a.x; r[1] = a.y; r[2] = a.z; r[3] = a.w;
    r[4] = b.x; r[5] = b.y; r[6] = b.z; r[7] = b.w;
}

__global__ void __launch_bounds__(H_DIM)
gaterec_kernel(const float* __restrict__ X,  const float* __restrict__ B,
               const float* __restrict__ G1, const float* __restrict__ G2,
               const float* __restrict__ G3, float* __restrict__ Out)
{
    extern __shared__ float smem[];
    float* in_t  = smem;                         // [2][NARR][TILE_F]
    float* out_t = smem + 2 * NARR * TILE_F;     // [TILE_F]

    __shared__ float hcol[2][H_DIM + 2];         // recurrent column, zero halos

    const int h = threadIdx.x;
    const size_t plane = (size_t)blockIdx.x * (H_DIM * W_DIM);

    const float* srcs[NARR] = { X + plane, B + plane, G1 + plane, G2 + plane, G3 + plane };

    hcol[0][h + 1] = 0.0f;
    if (h < 2) {
        hcol[0][h * (H_DIM + 1)] = 0.0f;
        hcol[1][h * (H_DIM + 1)] = 0.0f;
    }

    const uint32_t smem_u32 = (uint32_t)__cvta_generic_to_shared(in_t);

    // Coalesced chunk loader: per array, 4 float4 per thread.
    // j = t + 128*i -> row = j/4, c4 = j%4: each warp instr covers 8 consecutive
    // rows (8 gmem lines) x 4 float4 positions.
    auto load_chunk = [&](int c, int s) {
        const int cb = c * CW;                   // first column of chunk
        #pragma unroll
        for (int a = 0; a < NARR; ++a) {
            const float* src = srcs[a];
            const uint32_t dst_base = smem_u32 + (uint32_t)((s * NARR + a) * TILE_F) * 4u;
            #pragma unroll
            for (int i = 0; i < 4; ++i) {
                int j   = h + H_DIM * i;
                int row = j >> 2;
                int c4  = j & 3;
                cp_async16(dst_base + (uint32_t)(row * RSTRIDE + c4 * 4) * 4u,
                           src + row * W_DIM + cb + c4 * 4);
            }
        }
    };

    // Prologue: prefetch chunks 0 and 1.
    load_chunk(0, 0); cp_commit();
    load_chunk(1, 1); cp_commit();

    for (int c = 0; c < NCH; ++c) {
        cp_wait<1>();                            // chunk c landed
        __syncthreads();                         // visible to all; also orders
                                                 // prior out_t reads vs new STS

        const int s = c & 1;
        const float* tb = in_t + s * NARR * TILE_F;
        const int roff = h * RSTRIDE;

        #pragma unroll
        for (int sc = 0; sc < CW / SUB; ++sc) {
            float xv[SUB], bv[SUB], g1v[SUB], g2v[SUB], g3v[SUB];
            const int o = roff + sc * SUB;
            lds8(tb + 0 * TILE_F + o, xv);
            lds8(tb + 1 * TILE_F + o, bv);
            lds8(tb + 2 * TILE_F + o, g1v);
            lds8(tb + 3 * TILE_F + o, g2v);
            lds8(tb + 4 * TILE_F + o, g3v);

            #pragma unroll
            for (int i = 0; i < SUB; ++i) {
                const int cur = i & 1;           // SUB even -> phase resets per sub-chunk
                float up  = hcol[cur][h];
                float mid = hcol[cur][h + 1];
                float dn  = hcol[cur][h + 2];
                float hn = fmaf(bv[i], xv[i],
                           fmaf(g1v[i], up,
                           fmaf(g2v[i], mid, g3v[i] * dn)));
                hcol[cur ^ 1][h + 1] = hn;
                out_t[o + i] = hn;               // stride-20 rows: conflict-free STS
                __syncthreads();
            }
        }

        // Cooperative coalesced store of the finished 128x16 output tile.
        // Same 8-rows-per-warp mapping as the loader.
        {
            float* dst = Out + plane + (size_t)c * CW;
            #pragma unroll
            for (int i = 0; i < 4; ++i) {
                int j   = h + H_DIM * i;
                int row = j >> 2;
                int c4  = j & 3;
                float4 v = *(const float4*)(out_t + row * RSTRIDE + c4 * 4);
                *(float4*)(dst + row * W_DIM + c4 * 4) = v;
            }
        }

        // Prefetch chunk c+2 into the stage we just finished reading.
        if (c + 2 < NCH) load_chunk(c + 2, s);
        cp_commit();                             // commit (possibly empty) to keep
                                                 // the wait<1> accounting uniform
    }
}

extern "C" void kernel_launch(void* const* d_in, const int* in_sizes, int n_in,
                              void* d_out, int out_size) {
    const float* X  = (const float*)d_in[0];
    const float* B  = (const float*)d_in[1];
    const float* G1 = (const float*)d_in[2];
    const float* G2 = (const float*)d_in[3];
    const float* G3 = (const float*)d_in[4];
    float* Out = (float*)d_out;

    const int planes = in_sizes[0] / (H_DIM * W_DIM);       // N*C = 768
    const int dyn_smem = (2 * NARR * TILE_F + TILE_F) * 4;  // 112,640 B

    cudaFuncSetAttribute(gaterec_kernel,
                         cudaFuncAttributeMaxDynamicSharedMemorySize, dyn_smem);

    gaterec_kernel<<<planes, H_DIM, dyn_smem>>>(X, B, G1, G2, G3, Out);
}